// round 16
// baseline (speedup 1.0000x reference)
#include <cuda_runtime.h>

// MicroGPT forward, sm_103a. Fixed shapes.
#define NB  16
#define NT  2048
#define NC  16
#define NH  2
#define NHS 8
#define NL  2
#define NV  256
#define NTOK (NB*NT)
#define NQ  (NB*NH*NT)        // 65536 (bh, t) query slots
#define NSPLIT 4
#define EPSF 1e-5f
// (1/sqrt(HS)) * log2(e): q pre-scaled so softmax uses ex2 directly
#define QSCALE 0.5100700982280911f

typedef unsigned long long u64;

// Scratch (device globals; no dynamic allocation allowed)
__device__ float g_x[NTOK*NC];
__device__ float g_q[NQ*NHS];
__device__ float g_k[NQ*NHS];
__device__ float g_v[NQ*NHS];
__device__ float g_pacc[NSPLIT*NQ*NHS];   // split-K partial numerators
__device__ float g_pden[NSPLIT*NQ];       // split-K partial denominators

__device__ __forceinline__ float ex2f(float x){
    float y; asm("ex2.approx.f32 %0, %1;" : "=f"(y) : "f"(x)); return y;
}
__device__ __forceinline__ u64 fma2(u64 a, u64 b, u64 c){
    u64 d; asm("fma.rn.f32x2 %0, %1, %2, %3;" : "=l"(d) : "l"(a), "l"(b), "l"(c)); return d;
}
__device__ __forceinline__ u64 mul2(u64 a, u64 b){
    u64 d; asm("mul.rn.f32x2 %0, %1, %2;" : "=l"(d) : "l"(a), "l"(b)); return d;
}
__device__ __forceinline__ u64 add2(u64 a, u64 b){
    u64 d; asm("add.rn.f32x2 %0, %1, %2;" : "=l"(d) : "l"(a), "l"(b)); return d;
}
__device__ __forceinline__ u64 pack2(float lo, float hi){
    u64 r; asm("mov.b64 %0, {%1, %2};" : "=l"(r) : "f"(lo), "f"(hi)); return r;
}
__device__ __forceinline__ float2 unpack2(u64 v){
    float lo, hi; asm("mov.b64 {%0, %1}, %2;" : "=f"(lo), "=f"(hi) : "l"(v));
    return make_float2(lo, hi);
}

// ---------------------------------------------------------------------------
// 1) h = LN1(x); one of {q,k,v} = h @ W (q pre-scaled). Layer 0 only; fuses
//    the embedding. One thread per (type, head, token).
// ---------------------------------------------------------------------------
__global__ void __launch_bounds__(128) qkv_kernel(const float* __restrict__ wq,
                           const float* __restrict__ wk,
                           const float* __restrict__ wv,
                           const float* __restrict__ g1,
                           const float* __restrict__ b1,
                           const int*   __restrict__ idx,
                           const float* __restrict__ te,
                           const float* __restrict__ pe){
    __shared__ float sq[NH*NC*NHS], sk[NH*NC*NHS], sv[NH*NC*NHS];
    __shared__ float sg[NC], sb[NC];
    int tid = threadIdx.x;
    for (int i=tid; i<NH*NC*NHS; i+=128){ sq[i]=wq[i]; sk[i]=wk[i]; sv[i]=wv[i]; }
    if (tid < NC){ sg[tid]=g1[tid]; sb[tid]=b1[tid]; }
    __syncthreads();

    int gid  = blockIdx.x*128 + tid;
    int type = gid >> 16;              // 0=q, 1=k, 2=v (uniform per block)
    int rem  = gid & 0xFFFF;
    int head = rem >> 15;              // 0 or 1
    int tok  = rem & (NTOK-1);
    int b = tok >> 11;
    int t = tok & (NT-1);

    float xr[NC];
    {
        int id = idx[tok];
        const float4* t4 = (const float4*)te + id*4;
        const float4* p4 = (const float4*)pe + t*4;
        bool wr = (type==0) && (head==0);
        #pragma unroll
        for (int k=0;k<4;k++){
            float4 aa=t4[k], bb=p4[k];
            float4 r = make_float4(aa.x+bb.x, aa.y+bb.y, aa.z+bb.z, aa.w+bb.w);
            if (wr) ((float4*)g_x)[(size_t)tok*4 + k] = r;  // write once
            xr[4*k]=r.x; xr[4*k+1]=r.y; xr[4*k+2]=r.z; xr[4*k+3]=r.w;
        }
    }

    float m=0.f;
    #pragma unroll
    for (int c=0;c<NC;c++) m += xr[c];
    m *= (1.f/NC);
    float var=0.f;
    #pragma unroll
    for (int c=0;c<NC;c++){ float d=xr[c]-m; var += d*d; }
    var *= (1.f/NC);
    float inv = rsqrtf(var + EPSF);
    float h[NC];
    #pragma unroll
    for (int c=0;c<NC;c++) h[c] = (xr[c]-m)*inv*sg[c] + sb[c];

    const float* W = (type==0 ? sq : (type==1 ? sk : sv)) + head*NC*NHS;
    float acc[NHS];
    #pragma unroll
    for (int s=0;s<NHS;s++) acc[s]=0.f;
    #pragma unroll
    for (int c=0;c<NC;c++){
        float hc = h[c];
        #pragma unroll
        for (int s=0;s<NHS;s++) acc[s] += hc*W[c*NHS+s];
    }
    float scale = (type==0) ? QSCALE : 1.f;
    size_t obase = ((size_t)(b*NH+head)*NT + t)*NHS;
    float* dst = (type==0 ? g_q : (type==1 ? g_k : g_v)) + obase;
    ((float4*)dst)[0] = make_float4(acc[0]*scale, acc[1]*scale, acc[2]*scale, acc[3]*scale);
    ((float4*)dst)[1] = make_float4(acc[4]*scale, acc[5]*scale, acc[6]*scale, acc[7]*scale);
}

// ---------------------------------------------------------------------------
// 2) Causal attention, split-K mod-4 + dual-query + key-pair packed smem.
// ---------------------------------------------------------------------------
#define SCORE8(dst, q, kA, kB, kC, kD) \
    u64 dst = mul2(q[0], kA.x); \
    dst = fma2(q[1], kA.y, dst); \
    dst = fma2(q[2], kB.x, dst); \
    dst = fma2(q[3], kB.y, dst); \
    dst = fma2(q[4], kC.x, dst); \
    dst = fma2(q[5], kC.y, dst); \
    dst = fma2(q[6], kD.x, dst); \
    dst = fma2(q[7], kD.y, dst);

#define ACCUM8(acc, p, vA, vB, vC, vD) \
    acc[0]=fma2(p, vA.x, acc[0]); acc[1]=fma2(p, vA.y, acc[1]); \
    acc[2]=fma2(p, vB.x, acc[2]); acc[3]=fma2(p, vB.y, acc[3]); \
    acc[4]=fma2(p, vC.x, acc[4]); acc[5]=fma2(p, vC.y, acc[5]); \
    acc[6]=fma2(p, vD.x, acc[6]); acc[7]=fma2(p, vD.y, acc[7]);

__global__ void __launch_bounds__(128) attn_kernel(){
    int bh   = blockIdx.x;
    int a    = blockIdx.y;              // 0..7
    int s    = blockIdx.z;              // key-tile residue mod 4
    int lane = threadIdx.x;             // 0..127
    int b = 15 - a;

    const float4* kg = (const float4*)g_k + (size_t)bh*NT*2;
    const float4* vg = (const float4*)g_v + (size_t)bh*NT*2;

    int tA = a*128 + lane;
    int tB = b*128 + lane;

    u64 qa[8], qb[8];
    {
        const float4* qp = (const float4*)(g_q + ((size_t)bh*NT + tA)*NHS);
        float4 q0 = qp[0], q1 = qp[1];
        qa[0]=pack2(q0.x,q0.x); qa[1]=pack2(q0.y,q0.y);
        qa[2]=pack2(q0.z,q0.z); qa[3]=pack2(q0.w,q0.w);
        qa[4]=pack2(q1.x,q1.x); qa[5]=pack2(q1.y,q1.y);
        qa[6]=pack2(q1.z,q1.z); qa[7]=pack2(q1.w,q1.w);
        const float4* qq = (const float4*)(g_q + ((size_t)bh*NT + tB)*NHS);
        float4 r0 = qq[0], r1 = qq[1];
        qb[0]=pack2(r0.x,r0.x); qb[1]=pack2(r0.y,r0.y);
        qb[2]=pack2(r0.z,r0.z); qb[3]=pack2(r0.w,r0.w);
        qb[4]=pack2(r1.x,r1.x); qb[5]=pack2(r1.y,r1.y);
        qb[6]=pack2(r1.z,r1.z); qb[7]=pack2(r1.w,r1.w);
    }

    __shared__ u64 kq[64*10];   // 5120 B, key-pair packed
    __shared__ u64 vq[64*10];

    u64 accA[8], accB[8];
    #pragma unroll
    for (int c=0;c<8;c++){ accA[c]=0ull; accB[c]=0ull; }
    u64 denA2 = 0ull, denB2 = 0ull;

    for (int kt=s; kt<=b; kt+=NSPLIT){
        {
            float4 f0 = kg[kt*256 + lane*2];
            float4 f1 = kg[kt*256 + lane*2 + 1];
            float4 h0 = vg[kt*256 + lane*2];
            float4 h1 = vg[kt*256 + lane*2 + 1];
            int jp = lane>>1, jl = lane&1;
            float* kb = (float*)(kq + jp*10) + jl;
            kb[0]=f0.x; kb[2]=f0.y; kb[4]=f0.z; kb[6]=f0.w;
            kb[8]=f1.x; kb[10]=f1.y; kb[12]=f1.z; kb[14]=f1.w;
            float* vb = (float*)(vq + jp*10) + jl;
            vb[0]=h0.x; vb[2]=h0.y; vb[4]=h0.z; vb[6]=h0.w;
            vb[8]=h1.x; vb[10]=h1.y; vb[12]=h1.z; vb[14]=h1.w;
        }
        __syncthreads();

        if (kt < a){
            #pragma unroll 2
            for (int jj=0; jj<64; jj++){
                const ulonglong2* kp = (const ulonglong2*)(kq + jj*10);
                ulonglong2 kA=kp[0], kB=kp[1], kC=kp[2], kD=kp[3];
                SCORE8(sA, qa, kA,kB,kC,kD);
                SCORE8(sB, qb, kA,kB,kC,kD);
                float2 fa=unpack2(sA), fb=unpack2(sB);
                u64 pA = pack2(ex2f(fa.x), ex2f(fa.y));
                u64 pB = pack2(ex2f(fb.x), ex2f(fb.y));
                denA2 = add2(denA2, pA); denB2 = add2(denB2, pB);
                const ulonglong2* vp = (const ulonglong2*)(vq + jj*10);
                ulonglong2 vA=vp[0], vB=vp[1], vC=vp[2], vD=vp[3];
                ACCUM8(accA, pA, vA,vB,vC,vD);
                ACCUM8(accB, pB, vA,vB,vC,vD);
            }
        } else if (kt == a){
            #pragma unroll 2
            for (int jj=0; jj<64; jj++){
                const ulonglong2* kp = (const ulonglong2*)(kq + jj*10);
                ulonglong2 kA=kp[0], kB=kp[1], kC=kp[2], kD=kp[3];
                SCORE8(sA, qa, kA,kB,kC,kD);
                SCORE8(sB, qb, kA,kB,kC,kD);
                float2 fa=unpack2(sA), fb=unpack2(sB);
                float pa0 = ex2f(fa.x); if (2*jj   > lane) pa0 = 0.f;
                float pa1 = ex2f(fa.y); if (2*jj+1 > lane) pa1 = 0.f;
                u64 pA = pack2(pa0, pa1);
                u64 pB = pack2(ex2f(fb.x), ex2f(fb.y));
                denA2 = add2(denA2, pA); denB2 = add2(denB2, pB);
                const ulonglong2* vp = (const ulonglong2*)(vq + jj*10);
                ulonglong2 vA=vp[0], vB=vp[1], vC=vp[2], vD=vp[3];
                ACCUM8(accA, pA, vA,vB,vC,vD);
                ACCUM8(accB, pB, vA,vB,vC,vD);
            }
        } else if (kt < b){
            #pragma unroll 4
            for (int jj=0; jj<64; jj++){
                const ulonglong2* kp = (const ulonglong2*)(kq + jj*10);
                ulonglong2 kA=kp[0], kB=kp[1], kC=kp[2], kD=kp[3];
                SCORE8(sB, qb, kA,kB,kC,kD);
                float2 fb=unpack2(sB);
                u64 pB = pack2(ex2f(fb.x), ex2f(fb.y));
                denB2 = add2(denB2, pB);
                const ulonglong2* vp = (const ulonglong2*)(vq + jj*10);
                ulonglong2 vA=vp[0], vB=vp[1], vC=vp[2], vD=vp[3];
                ACCUM8(accB, pB, vA,vB,vC,vD);
            }
        } else {
            int jje = lane>>1;
            #pragma unroll 4
            for (int jj=0; jj<jje; jj++){
                const ulonglong2* kp = (const ulonglong2*)(kq + jj*10);
                ulonglong2 kA=kp[0], kB=kp[1], kC=kp[2], kD=kp[3];
                SCORE8(sB, qb, kA,kB,kC,kD);
                float2 fb=unpack2(sB);
                u64 pB = pack2(ex2f(fb.x), ex2f(fb.y));
                denB2 = add2(denB2, pB);
                const ulonglong2* vp = (const ulonglong2*)(vq + jj*10);
                ulonglong2 vA=vp[0], vB=vp[1], vC=vp[2], vD=vp[3];
                ACCUM8(accB, pB, vA,vB,vC,vD);
            }
            {
                int jj = jje;
                const ulonglong2* kp = (const ulonglong2*)(kq + jj*10);
                ulonglong2 kA=kp[0], kB=kp[1], kC=kp[2], kD=kp[3];
                SCORE8(sB, qb, kA,kB,kC,kD);
                float2 fb=unpack2(sB);
                float pb0 = ex2f(fb.x);
                float pb1 = (lane & 1) ? ex2f(fb.y) : 0.f;
                u64 pB = pack2(pb0, pb1);
                denB2 = add2(denB2, pB);
                const ulonglong2* vp = (const ulonglong2*)(vq + jj*10);
                ulonglong2 vA=vp[0], vB=vp[1], vC=vp[2], vD=vp[3];
                ACCUM8(accB, pB, vA,vB,vC,vD);
            }
        }
        __syncthreads();
    }

    int pAi = bh*NT + tA;
    int pBi = bh*NT + tB;
    {
        float2 d = unpack2(denA2);
        g_pden[s*NQ + pAi] = d.x + d.y;
        float r[8];
        #pragma unroll
        for (int c=0;c<8;c++){ float2 f=unpack2(accA[c]); r[c]=f.x+f.y; }
        float4* op = (float4*)(g_pacc + ((size_t)s*NQ + pAi)*NHS);
        op[0] = make_float4(r[0],r[1],r[2],r[3]);
        op[1] = make_float4(r[4],r[5],r[6],r[7]);
    }
    {
        float2 d = unpack2(denB2);
        g_pden[s*NQ + pBi] = d.x + d.y;
        float r[8];
        #pragma unroll
        for (int c=0;c<8;c++){ float2 f=unpack2(accB[c]); r[c]=f.x+f.y; }
        float4* op = (float4*)(g_pacc + ((size_t)s*NQ + pBi)*NHS);
        op[0] = make_float4(r[0],r[1],r[2],r[3]);
        op[1] = make_float4(r[4],r[5],r[6],r[7]);
    }
}

// ---------------------------------------------------------------------------
// 3) Fused: combine(splits) -> x += o@Wo^T -> LN2 -> MLP residual
//          [-> LN1 -> next-layer q,k,v]  (do_qkv)
//    TWO threads per token (lane pair). Work split by half everywhere:
//    - combine + Wo partial: each thread handles ITS head's 8 o-dims,
//      butterfly merges the 16 Wo partials.
//    - LN duplicated (cheap).
//    - MLP: 32 hidden units each, butterfly merges deltas.
//    - qkv: half h computes q,k,v of head h.
// ---------------------------------------------------------------------------
__global__ void __launch_bounds__(128) post_kernel(const float* __restrict__ wo,
                            const float* __restrict__ g2,
                            const float* __restrict__ b2,
                            const float* __restrict__ w1,
                            const float* __restrict__ w2,
                            const float* __restrict__ nwq,
                            const float* __restrict__ nwk,
                            const float* __restrict__ nwv,
                            const float* __restrict__ ng1,
                            const float* __restrict__ nb1,
                            int do_qkv){
    __shared__ __align__(16) float s_wo[NC*NC];
    __shared__ __align__(16) float s_w1[4*NC*NC];
    __shared__ __align__(16) float s_w2[4*NC*NC];   // [j][i] = w2[i][j]
    __shared__ __align__(16) float sq[NH*NC*NHS], sk[NH*NC*NHS], sv[NH*NC*NHS];
    __shared__ float sg[NC], sb[NC], ng[NC], nb[NC];
    int tid = threadIdx.x;
    for (int i=tid; i<NC*NC; i+=128) s_wo[i] = wo[i];
    for (int i=tid; i<4*NC*NC; i+=128) s_w1[i] = w1[i];
    for (int idx=tid; idx<4*NC*NC; idx+=128){
        int j = idx >> 4, i = idx & 15;
        s_w2[idx] = w2[i*(4*NC) + j];
    }
    if (do_qkv){
        for (int i=tid; i<NH*NC*NHS; i+=128){ sq[i]=nwq[i]; sk[i]=nwk[i]; sv[i]=nwv[i]; }
        if (tid < NC){ ng[tid]=ng1[tid]; nb[tid]=nb1[tid]; }
    }
    if (tid < NC){ sg[tid]=g2[tid]; sb[tid]=b2[tid]; }
    __syncthreads();

    int gid  = blockIdx.x*128 + tid;
    int half = gid & 1;                 // my head / my split
    int tok  = gid >> 1;
    int b = tok >> 11;
    int t = tok & (NT-1);
    int ph = (b*NH + half)*NT + t;      // my head's query slot

    // --- combine my head's splits: o_h = Σacc/Σden (8 floats -> 4 u64) ---
    float den = 0.f;
    #pragma unroll
    for (int s=0;s<NSPLIT;s++) den += g_pden[s*NQ + ph];
    float4 A0=make_float4(0,0,0,0), A1=make_float4(0,0,0,0);
    #pragma unroll
    for (int s=0;s<NSPLIT;s++){
        const float4* ap = (const float4*)(g_pacc + ((size_t)s*NQ + ph)*NHS);
        float4 x0=ap[0], x1=ap[1];
        A0.x+=x0.x; A0.y+=x0.y; A0.z+=x0.z; A0.w+=x0.w;
        A1.x+=x1.x; A1.y+=x1.y; A1.z+=x1.z; A1.w+=x1.w;
    }
    float iv = 1.f/den;
    u64 oh[4];
    oh[0] = pack2(A0.x*iv, A0.y*iv);
    oh[1] = pack2(A0.z*iv, A0.w*iv);
    oh[2] = pack2(A1.x*iv, A1.y*iv);
    oh[3] = pack2(A1.z*iv, A1.w*iv);

    // --- Wo partial over my 8 o-dims, all 16 outputs ---
    float part[NC];
    #pragma unroll
    for (int i=0;i<NC;i++){
        const ulonglong2* wr = (const ulonglong2*)(s_wo + i*NC) + 2*half;
        ulonglong2 w0 = wr[0], w1r = wr[1];
        u64 s2 = mul2(oh[0], w0.x);
        s2 = fma2(oh[1], w0.y, s2);
        s2 = fma2(oh[2], w1r.x, s2);
        s2 = fma2(oh[3], w1r.y, s2);
        float2 f = unpack2(s2);
        part[i] = f.x + f.y;
    }
    // butterfly: add partner's partials (other head)
    u64 pp[8];
    #pragma unroll
    for (int i=0;i<8;i++) pp[i] = pack2(part[2*i], part[2*i+1]);
    #pragma unroll
    for (int i=0;i<8;i++){
        u64 o = __shfl_xor_sync(0xffffffffu, pp[i], 1);
        pp[i] = add2(pp[i], o);
    }

    // --- xr = x + wo_full (both threads identical from here) ---
    float xr[NC];
    {
        const float4* x4 = (const float4*)g_x + (size_t)tok*4;
        #pragma unroll
        for (int k=0;k<4;k++){
            float4 v=x4[k];
            float2 e = unpack2(pp[2*k]);
            float2 f = unpack2(pp[2*k+1]);
            xr[4*k]=v.x+e.x; xr[4*k+1]=v.y+e.y; xr[4*k+2]=v.z+f.x; xr[4*k+3]=v.w+f.y;
        }
    }

    // --- LN2 (duplicated) ---
    float m=0.f;
    #pragma unroll
    for (int c=0;c<NC;c++) m += xr[c];
    m *= (1.f/NC);
    float var=0.f;
    #pragma unroll
    for (int c=0;c<NC;c++){ float d=xr[c]-m; var += d*d; }
    var *= (1.f/NC);
    float inv = rsqrtf(var + EPSF);
    u64 hp[8];
    #pragma unroll
    for (int c=0;c<NC;c+=2){
        float h0 = (xr[c]-m)*inv*sg[c] + sb[c];
        float h1 = (xr[c+1]-m)*inv*sg[c+1] + sb[c+1];
        hp[c>>1] = pack2(h0, h1);
    }

    // --- MLP half: j in [half*32, half*32+32) ---
    u64 d0=0,d1=0,d2=0,d3=0,d4=0,d5=0,d6=0,d7=0;
    int j0 = half*32;
    #pragma unroll 4
    for (int jj=0;jj<32;jj++){
        int j = j0 + jj;
        const ulonglong2* wr = (const ulonglong2*)(s_w1 + j*NC);
        ulonglong2 a0 = wr[0], a1 = wr[1], a2 = wr[2], a3 = wr[3];
        u64 y2 = mul2(hp[0], a0.x);
        y2 = fma2(hp[1], a0.y, y2);
        y2 = fma2(hp[2], a1.x, y2);
        y2 = fma2(hp[3], a1.y, y2);
        y2 = fma2(hp[4], a2.x, y2);
        y2 = fma2(hp[5], a2.y, y2);
        y2 = fma2(hp[6], a3.x, y2);
        y2 = fma2(hp[7], a3.y, y2);
        float2 yf = unpack2(y2);
        float yv = fmaxf(yf.x + yf.y, 0.f);
        u64 yy = pack2(yv, yv);
        const ulonglong2* cr = (const ulonglong2*)(s_w2 + j*NC);
        ulonglong2 c0 = cr[0], c1 = cr[1], c2 = cr[2], c3 = cr[3];
        d0 = fma2(yy, c0.x, d0);
        d1 = fma2(yy, c0.y, d1);
        d2 = fma2(yy, c1.x, d2);
        d3 = fma2(yy, c1.y, d3);
        d4 = fma2(yy, c2.x, d4);
        d5 = fma2(yy, c2.y, d5);
        d6 = fma2(yy, c3.x, d6);
        d7 = fma2(yy, c3.y, d7);
    }
    // butterfly: merge the two halves' deltas
    d0 = add2(d0, __shfl_xor_sync(0xffffffffu, d0, 1));
    d1 = add2(d1, __shfl_xor_sync(0xffffffffu, d1, 1));
    d2 = add2(d2, __shfl_xor_sync(0xffffffffu, d2, 1));
    d3 = add2(d3, __shfl_xor_sync(0xffffffffu, d3, 1));
    d4 = add2(d4, __shfl_xor_sync(0xffffffffu, d4, 1));
    d5 = add2(d5, __shfl_xor_sync(0xffffffffu, d5, 1));
    d6 = add2(d6, __shfl_xor_sync(0xffffffffu, d6, 1));
    d7 = add2(d7, __shfl_xor_sync(0xffffffffu, d7, 1));

    float2 e0=unpack2(d0), e1=unpack2(d1), e2=unpack2(d2), e3=unpack2(d3);
    float2 e4=unpack2(d4), e5=unpack2(d5), e6=unpack2(d6), e7=unpack2(d7);
    xr[0]+=e0.x; xr[1]+=e0.y; xr[2]+=e1.x; xr[3]+=e1.y;
    xr[4]+=e2.x; xr[5]+=e2.y; xr[6]+=e3.x; xr[7]+=e3.y;
    xr[8]+=e4.x; xr[9]+=e4.y; xr[10]+=e5.x; xr[11]+=e5.y;
    xr[12]+=e6.x; xr[13]+=e6.y; xr[14]+=e7.x; xr[15]+=e7.y;

    // --- store x (split halves between the pair) ---
    float4* xo = (float4*)g_x + (size_t)tok*4;
    if (half == 0){
        xo[0] = make_float4(xr[0], xr[1], xr[2], xr[3]);
        xo[1] = make_float4(xr[4], xr[5], xr[6], xr[7]);
    } else {
        xo[2] = make_float4(xr[8], xr[9], xr[10], xr[11]);
        xo[3] = make_float4(xr[12], xr[13], xr[14], xr[15]);
    }

    // --- fused next-layer qkv: half h computes q,k,v of head h ---
    if (do_qkv){
        float m1=0.f;
        #pragma unroll
        for (int c=0;c<NC;c++) m1 += xr[c];
        m1 *= (1.f/NC);
        float v1=0.f;
        #pragma unroll
        for (int c=0;c<NC;c++){ float d=xr[c]-m1; v1 += d*d; }
        v1 *= (1.f/NC);
        float i1 = rsqrtf(v1 + EPSF);
        u64 hc2[NC];
        #pragma unroll
        for (int c=0;c<NC;c++){
            float hv = (xr[c]-m1)*i1*ng[c] + nb[c];
            hc2[c] = pack2(hv, hv);
        }
        size_t obase = ((size_t)(b*NH+half)*NT + t)*NHS;
        const float* Wbase[3] = { sq + half*NC*NHS, sk + half*NC*NHS, sv + half*NC*NHS };
        float* Dst[3] = { g_q + obase, g_k + obase, g_v + obase };
        #pragma unroll
        for (int ty=0; ty<3; ty++){
            const float* W = Wbase[ty];
            u64 ac[4]; ac[0]=0; ac[1]=0; ac[2]=0; ac[3]=0;
            #pragma unroll
            for (int c=0;c<NC;c++){
                const ulonglong2* wr = (const ulonglong2*)(W + c*NHS);
                ulonglong2 w = wr[0];
                ac[0] = fma2(hc2[c], w.x, ac[0]);
                ac[1] = fma2(hc2[c], w.y, ac[1]);
                ulonglong2 w2v = wr[1];
                ac[2] = fma2(hc2[c], w2v.x, ac[2]);
                ac[3] = fma2(hc2[c], w2v.y, ac[3]);
            }
            float sc = (ty==0) ? QSCALE : 1.f;
            float2 r0=unpack2(ac[0]), r1=unpack2(ac[1]), r2=unpack2(ac[2]), r3=unpack2(ac[3]);
            float4* dp = (float4*)Dst[ty];
            dp[0] = make_float4(r0.x*sc, r0.y*sc, r1.x*sc, r1.y*sc);
            dp[1] = make_float4(r2.x*sc, r2.y*sc, r3.x*sc, r3.y*sc);
        }
    }
}

// ---------------------------------------------------------------------------
// 4) h = LNf(x); logits = h @ tok_emb^T.
// ---------------------------------------------------------------------------
__global__ void __launch_bounds__(NV) head_kernel(const float* __restrict__ te,
                                                  const float* __restrict__ gf,
                                                  const float* __restrict__ bf,
                                                  float* __restrict__ out){
    int tid  = threadIdx.x;
    int warp = tid >> 5, lane = tid & 31;
    int tok0 = blockIdx.x * 16;
    __shared__ __align__(16) float hs[16][NC];

    {
        int sub = lane >> 4;           // 0 or 1
        int c   = lane & 15;
        int tok = tok0 + warp*2 + sub;
        float val = g_x[(size_t)tok*NC + c];
        float s = val;
        #pragma unroll
        for (int o=8;o>0;o>>=1) s += __shfl_xor_sync(0xffffffffu, s, o, 16);
        float m = s * (1.f/NC);
        float d = val - m;
        float vv = d*d;
        #pragma unroll
        for (int o=8;o>0;o>>=1) vv += __shfl_xor_sync(0xffffffffu, vv, o, 16);
        float inv = rsqrtf(vv*(1.f/NC) + EPSF);
        hs[warp*2+sub][c] = d*inv*gf[c] + bf[c];
    }
    __syncthreads();

    int v = tid;
    const ulonglong2* tr = (const ulonglong2*)te + v*4;
    ulonglong2 t0 = tr[0], t1 = tr[1], t2 = tr[2], t3 = tr[3];

    #pragma unroll 4
    for (int k=0;k<16;k++){
        const ulonglong2* hp = (const ulonglong2*)hs[k];
        ulonglong2 h0 = hp[0], h1 = hp[1];
        u64 s2 = mul2(h0.x, t0.x);
        s2 = fma2(h0.y, t0.y, s2);
        s2 = fma2(h1.x, t1.x, s2);
        s2 = fma2(h1.y, t1.y, s2);
        ulonglong2 h2 = hp[2], h3 = hp[3];
        s2 = fma2(h2.x, t2.x, s2);
        s2 = fma2(h2.y, t2.y, s2);
        s2 = fma2(h3.x, t3.x, s2);
        s2 = fma2(h3.y, t3.y, s2);
        float2 f = unpack2(s2);
        out[(size_t)(tok0+k)*NV + v] = f.x + f.y;
    }
}

// ---------------------------------------------------------------------------
extern "C" void kernel_launch(void* const* d_in, const int* in_sizes, int n_in,
                              void* d_out, int out_size){
    const int*   idx  = (const int*)  d_in[0];
    const float* te   = (const float*)d_in[1];
    const float* pe   = (const float*)d_in[2];
    const float* wq   = (const float*)d_in[3];
    const float* wk   = (const float*)d_in[4];
    const float* wv   = (const float*)d_in[5];
    const float* wo   = (const float*)d_in[6];
    const float* ln1g = (const float*)d_in[7];
    const float* ln1b = (const float*)d_in[8];
    const float* ln2g = (const float*)d_in[9];
    const float* ln2b = (const float*)d_in[10];
    const float* w1   = (const float*)d_in[11];
    const float* w2   = (const float*)d_in[12];
    const float* lnfg = (const float*)d_in[13];
    const float* lnfb = (const float*)d_in[14];
    float* out = (float*)d_out;

    // layer 0 qkv (embedding fused)
    qkv_kernel<<<NTOK*NH*3/128, 128>>>(wq, wk, wv, ln1g, ln1b, idx, te, pe);

    dim3 ag(NB*NH, 8, NSPLIT);
    // layer 0 attention + post (fused with layer 1 qkv)
    attn_kernel<<<ag, 128>>>();
    post_kernel<<<NTOK*2/128, 128>>>(wo, ln2g, ln2b, w1, w2,
                                     wq + NH*NC*NHS, wk + NH*NC*NHS, wv + NH*NC*NHS,
                                     ln1g + NC, ln1b + NC, 1);
    // layer 1 attention + post (no qkv)
    attn_kernel<<<ag, 128>>>();
    post_kernel<<<NTOK*2/128, 128>>>(wo + NC*NC, ln2g + NC, ln2b + NC,
                                     w1 + 4*NC*NC, w2 + 4*NC*NC,
                                     wq, wk, wv, ln1g, ln1b, 0);

    head_kernel<<<NTOK/16, NV>>>(te, lnfg, lnfb, out);
}